// round 4
// baseline (speedup 1.0000x reference)
#include <cuda_runtime.h>

#define BSZ   8
#define NN    20000
#define FIN   256
#define NH    8
#define ND    64
#define EE    160000

#define GX    74         // grid.x for k_scores (74*8 blocks = 2 waves of 296)

typedef unsigned long long ull;

// Scratch (device globals — no allocation allowed)
__device__ float g_u[BSZ * 2 * NH * FIN];          // [b][o][f], o = s*8+h
__device__ float g_scores[2][BSZ * NN * NH];       // [s][(b*N+n)*8+h]
__device__ int   g_idx_is64;

__device__ __forceinline__ void fma2(ull& d, ull a, ull b) {
    asm("fma.rn.f32x2 %0, %1, %2, %0;" : "+l"(d) : "l"(a), "l"(b));
}
__device__ __forceinline__ void upk2(ull v, float& lo, float& hi) {
    asm("mov.b64 {%0, %1}, %2;" : "=f"(lo), "=f"(hi) : "l"(v));
}

// ---------------------------------------------------------------------------
// K0: sniff index dtype (int64 -> odd 32-bit words all zero).
// ---------------------------------------------------------------------------
__global__ void k_sniff(const unsigned int* __restrict__ head_words) {
    __shared__ int any_nonzero;
    if (threadIdx.x == 0) any_nonzero = 0;
    __syncthreads();
    for (int i = threadIdx.x; i < 1024; i += blockDim.x)
        if (head_words[2 * i + 1] != 0u) any_nonzero = 1;
    __syncthreads();
    if (threadIdx.x == 0) g_idx_is64 = any_nonzero ? 0 : 1;
}

// ---------------------------------------------------------------------------
// K1: u[b][o][f] = sum_d W[h*64+d][f] * scoring_{s}[b][h][d],  o = s*8+h
// ---------------------------------------------------------------------------
__global__ void k_prep(const float* __restrict__ W,
                       const float* __restrict__ src,
                       const float* __restrict__ trg) {
    int blk = blockIdx.x;
    int h = blk & 7;
    int s = (blk >> 3) & 1;
    int b = blk >> 4;
    int f = threadIdx.x;

    __shared__ float sc[ND];
    const float* scp = (s == 0 ? src : trg) + (b * NH + h) * ND;
    if (threadIdx.x < ND) sc[threadIdx.x] = scp[threadIdx.x];
    __syncthreads();

    const float* Wp = W + (h * ND) * FIN + f;
    float acc = 0.f;
#pragma unroll 8
    for (int d = 0; d < ND; d++) acc = fmaf(Wp[d * FIN], sc[d], acc);
    g_u[((b * 2 + s) * NH + h) * FIN + f] = acc;
}

// ---------------------------------------------------------------------------
// K2: scores[(b,n,o)] = sum_f ch[b][n][f] * u[b][o][f]
//
// Lane map: og = lane>>3 (4 outs), fc = lane&7 (16B chunk within 128B block).
// Per warp-LDG of row r at f-block fi: lanes cover ONE 128B line (og lanes
// broadcast) -> 1 L1 wavefront, fully consumed.
// Thread: 4 rows x 4 outs, 16 packed-f32x2 accumulators.
// u in smem; each u-LDS.128 8-lane subgroup reads 128B contiguous ->
// conflict-free at the 4-phase floor.
// Reduce across 8 fc lanes with 3 shfl_xor; lane fc==0 stores float4.
// ---------------------------------------------------------------------------
__global__ void __launch_bounds__(256, 2)
k_scores(const float* __restrict__ ch) {
    __shared__ float u_s[16 * 256];     // [o][f], 16 KB
    const int b = blockIdx.y;

    // Cooperative load of u[b] (1024 float4, coalesced).
    for (int e = threadIdx.x; e < 1024; e += 256)
        ((float4*)u_s)[e] = ((const float4*)(g_u + b * 4096))[e];
    __syncthreads();

    const int w     = threadIdx.x >> 5;
    const int lane  = threadIdx.x & 31;
    const int og    = lane >> 3;
    const int fc    = lane & 7;
    const int s_tab = og >> 1;
    const int hoff  = (og & 1) * 4;

    const float* chb = ch + (size_t)b * NN * FIN;
    const ulonglong2* us = (const ulonglong2*)u_s;   // 16B units: o*64 + fi*8 + fc
    const int ub0 = (og * 4 + 0) * 64 + fc;
    const int ub1 = (og * 4 + 1) * 64 + fc;
    const int ub2 = (og * 4 + 2) * 64 + fc;
    const int ub3 = (og * 4 + 3) * 64 + fc;

    const int stride = GX * 32;  // rows covered per grid-x sweep

    for (int rb = blockIdx.x * 32 + w * 4; rb < NN; rb += stride) {
        // NN % 4 == 0 and rb % 4 == 0 -> all 4 rows valid.
        const ulonglong2* p0 = (const ulonglong2*)(chb + (size_t)(rb + 0) * FIN) + fc;
        const ulonglong2* p1 = (const ulonglong2*)(chb + (size_t)(rb + 1) * FIN) + fc;
        const ulonglong2* p2 = (const ulonglong2*)(chb + (size_t)(rb + 2) * FIN) + fc;
        const ulonglong2* p3 = (const ulonglong2*)(chb + (size_t)(rb + 3) * FIN) + fc;

        ull acc[4][4];
#pragma unroll
        for (int r = 0; r < 4; r++)
#pragma unroll
            for (int k = 0; k < 4; k++) acc[r][k] = 0ull;

#pragma unroll
        for (int fi = 0; fi < 8; fi++) {
            ulonglong2 c0 = p0[fi * 8];
            ulonglong2 c1 = p1[fi * 8];
            ulonglong2 c2 = p2[fi * 8];
            ulonglong2 c3 = p3[fi * 8];
            ulonglong2 u0 = us[ub0 + fi * 8];
            ulonglong2 u1 = us[ub1 + fi * 8];
            ulonglong2 u2 = us[ub2 + fi * 8];
            ulonglong2 u3 = us[ub3 + fi * 8];

            fma2(acc[0][0], c0.x, u0.x); fma2(acc[0][0], c0.y, u0.y);
            fma2(acc[0][1], c0.x, u1.x); fma2(acc[0][1], c0.y, u1.y);
            fma2(acc[0][2], c0.x, u2.x); fma2(acc[0][2], c0.y, u2.y);
            fma2(acc[0][3], c0.x, u3.x); fma2(acc[0][3], c0.y, u3.y);

            fma2(acc[1][0], c1.x, u0.x); fma2(acc[1][0], c1.y, u0.y);
            fma2(acc[1][1], c1.x, u1.x); fma2(acc[1][1], c1.y, u1.y);
            fma2(acc[1][2], c1.x, u2.x); fma2(acc[1][2], c1.y, u2.y);
            fma2(acc[1][3], c1.x, u3.x); fma2(acc[1][3], c1.y, u3.y);

            fma2(acc[2][0], c2.x, u0.x); fma2(acc[2][0], c2.y, u0.y);
            fma2(acc[2][1], c2.x, u1.x); fma2(acc[2][1], c2.y, u1.y);
            fma2(acc[2][2], c2.x, u2.x); fma2(acc[2][2], c2.y, u2.y);
            fma2(acc[2][3], c2.x, u3.x); fma2(acc[2][3], c2.y, u3.y);

            fma2(acc[3][0], c3.x, u0.x); fma2(acc[3][0], c3.y, u0.y);
            fma2(acc[3][1], c3.x, u1.x); fma2(acc[3][1], c3.y, u1.y);
            fma2(acc[3][2], c3.x, u2.x); fma2(acc[3][2], c3.y, u2.y);
            fma2(acc[3][3], c3.x, u3.x); fma2(acc[3][3], c3.y, u3.y);
        }

        // Epilogue: packed-halves add, reduce over fc lanes, store float4.
        float v[4][4];
#pragma unroll
        for (int r = 0; r < 4; r++)
#pragma unroll
            for (int k = 0; k < 4; k++) {
                float lo, hi; upk2(acc[r][k], lo, hi);
                v[r][k] = lo + hi;
            }
#pragma unroll
        for (int m = 1; m <= 4; m <<= 1)
#pragma unroll
            for (int r = 0; r < 4; r++)
#pragma unroll
                for (int k = 0; k < 4; k++)
                    v[r][k] += __shfl_xor_sync(0xffffffffu, v[r][k], m);

        if (fc == 0) {
#pragma unroll
            for (int r = 0; r < 4; r++) {
                float4 o4 = make_float4(v[r][0], v[r][1], v[r][2], v[r][3]);
                *(float4*)&g_scores[s_tab][((size_t)b * NN + rb + r) * NH + hoff] = o4;
            }
        }
    }
}

// ---------------------------------------------------------------------------
// K3: out[i] = sigmoid(scores_src[head[i]] + scores_trg[tail[i]])
// 8 edges per thread for deep MLP against L2 latency.
// ---------------------------------------------------------------------------
__global__ void k_gather(const void* __restrict__ head,
                         const void* __restrict__ tail,
                         float* __restrict__ out, int total) {
    int i = blockIdx.x * blockDim.x + threadIdx.x;   // group of 8 edges
    if (i * 8 >= total) return;

    long long h[8], t[8];
    if (g_idx_is64) {
        const longlong2* hp = (const longlong2*)head + 4 * i;
        const longlong2* tp = (const longlong2*)tail + 4 * i;
#pragma unroll
        for (int k = 0; k < 4; k++) {
            longlong2 a = hp[k]; h[2 * k] = a.x; h[2 * k + 1] = a.y;
            longlong2 c = tp[k]; t[2 * k] = c.x; t[2 * k + 1] = c.y;
        }
    } else {
        const int4* hp = (const int4*)head + 2 * i;
        const int4* tp = (const int4*)tail + 2 * i;
#pragma unroll
        for (int k = 0; k < 2; k++) {
            int4 a = hp[k];
            h[4 * k] = a.x; h[4 * k + 1] = a.y; h[4 * k + 2] = a.z; h[4 * k + 3] = a.w;
            int4 c = tp[k];
            t[4 * k] = c.x; t[4 * k + 1] = c.y; t[4 * k + 2] = c.z; t[4 * k + 3] = c.w;
        }
    }

    float sh[8], st[8];
#pragma unroll
    for (int k = 0; k < 8; k++) sh[k] = g_scores[0][h[k]];
#pragma unroll
    for (int k = 0; k < 8; k++) st[k] = g_scores[1][t[k]];

    float4 r0, r1;
    float* rp = (float*)&r0;
#pragma unroll
    for (int k = 0; k < 8; k++) {
        float x = sh[k] + st[k];
        ((k < 4) ? ((float*)&r0) : ((float*)&r1))[k & 3] = 1.f / (1.f + __expf(-x));
    }
    (void)rp;
    ((float4*)out)[2 * i]     = r0;
    ((float4*)out)[2 * i + 1] = r1;
}

// ---------------------------------------------------------------------------
extern "C" void kernel_launch(void* const* d_in, const int* in_sizes, int n_in,
                              void* d_out, int out_size) {
    const float* ch   = (const float*)d_in[0];
    const void*  head = d_in[1];
    const void*  tail = d_in[2];
    const float* W    = (const float*)d_in[3];
    const float* src  = (const float*)d_in[4];
    const float* trg  = (const float*)d_in[5];
    float* out = (float*)d_out;

    k_sniff<<<1, 256>>>((const unsigned int*)head);
    k_prep<<<BSZ * 2 * NH, 256>>>(W, src, trg);

    dim3 g2(GX, BSZ);
    k_scores<<<g2, 256>>>(ch);

    int total = BSZ * EE;                       // 1,280,000 (multiple of 8)
    int groups = total / 8;
    k_gather<<<(groups + 255) / 256, 256>>>(head, tail, out, total);
}

// round 5
// speedup vs baseline: 1.6692x; 1.6692x over previous
#include <cuda_runtime.h>

#define BSZ   8
#define NN    20000
#define FIN   256
#define NH    8
#define ND    64
#define EE    160000

#define GX    37         // grid.x: 37*8 = 296 blocks = one full wave at occ 2
#define NTILES 313       // ceil(20000 / 64)

typedef unsigned long long ull;

// Scratch (device globals — no allocation allowed)
__device__ float g_u[BSZ * 2 * NH * FIN];          // [b][o][f], o = s*8+h
__device__ float g_scores[2][BSZ * NN * NH];       // [s][(b*N+n)*8+h]
__device__ int   g_idx_is64;

__device__ __forceinline__ void fma2(ull& d, ull a, ull b) {
    asm("fma.rn.f32x2 %0, %1, %2, %0;" : "+l"(d) : "l"(a), "l"(b));
}
__device__ __forceinline__ void upk2(ull v, float& lo, float& hi) {
    asm("mov.b64 {%0, %1}, %2;" : "=f"(lo), "=f"(hi) : "l"(v));
}

// ---------------------------------------------------------------------------
// K0: sniff index dtype (int64 -> odd 32-bit words all zero).
// ---------------------------------------------------------------------------
__global__ void k_sniff(const unsigned int* __restrict__ head_words) {
    __shared__ int any_nonzero;
    if (threadIdx.x == 0) any_nonzero = 0;
    __syncthreads();
    for (int i = threadIdx.x; i < 1024; i += blockDim.x)
        if (head_words[2 * i + 1] != 0u) any_nonzero = 1;
    __syncthreads();
    if (threadIdx.x == 0) g_idx_is64 = any_nonzero ? 0 : 1;
}

// ---------------------------------------------------------------------------
// K1: u[b][o][f] = sum_d W[h*64+d][f] * scoring_{s}[b][h][d],  o = s*8+h
// ---------------------------------------------------------------------------
__global__ void k_prep(const float* __restrict__ W,
                       const float* __restrict__ src,
                       const float* __restrict__ trg) {
    int blk = blockIdx.x;
    int h = blk & 7;
    int s = (blk >> 3) & 1;
    int b = blk >> 4;
    int f = threadIdx.x;

    __shared__ float sc[ND];
    const float* scp = (s == 0 ? src : trg) + (b * NH + h) * ND;
    if (threadIdx.x < ND) sc[threadIdx.x] = scp[threadIdx.x];
    __syncthreads();

    const float* Wp = W + (h * ND) * FIN + f;
    float acc = 0.f;
#pragma unroll 8
    for (int d = 0; d < ND; d++) acc = fmaf(Wp[d * FIN], sc[d], acc);
    g_u[((b * 2 + s) * NH + h) * FIN + f] = acc;
}

// ---------------------------------------------------------------------------
// K2: scores[(b,n,o)] = sum_f ch[b][n][f] * u[b][o][f]
//
// Lane map: og = lane&3 (4 outs each), rl = (lane>>2)&1 (row of pair),
//           fc = lane>>3 (16B chunk within 64B step).
// Warp-iter: 8 rows (4 row-pairs) x 16 outs; fi steps 16x 64B over the row.
// acc = 4rp x 4o packed f32x2 (32 regs). 1-deep prefetch on c.
// u smem XOR-swizzled by og -> every u LDS.128 phase conflict-free.
// Reduce across fc lanes with 2 shfl_xor; lanes fc==0 store float4.
// ---------------------------------------------------------------------------
__global__ void __launch_bounds__(256, 2)
k_scores(const float* __restrict__ ch) {
    __shared__ float u_s[16 * 256];     // swizzled [o][chunk^og_swz][4], 16 KB
    const int b = blockIdx.y;

    // Load u[b] swizzled: chunk' = chunk ^ ((o>>2)&3).
    for (int e = threadIdx.x; e < 4096; e += 256) {
        int o = e >> 8, f = e & 255;
        int chunk = f >> 2, within = f & 3;
        int chs = chunk ^ ((o >> 2) & 3);
        u_s[o * 256 + chs * 4 + within] = g_u[b * 4096 + e];
    }
    __syncthreads();

    const int w    = threadIdx.x >> 5;
    const int lane = threadIdx.x & 31;
    const int og   = lane & 3;
    const int rl   = (lane >> 2) & 1;
    const int fc   = lane >> 3;
    const int fcx  = fc ^ og;                    // swizzled chunk low bits
    const int s_tab = og >> 1;
    const int hoff  = (og & 1) * 4;

    const float* chb = ch + (size_t)b * NN * FIN;
    const ulonglong2* us = (const ulonglong2*)u_s;   // 16B units: o*64 + chunk
    // Per-k u base indices (16B units), fi adds fi*4.
    const int ub0 = (og * 4 + 0) * 64 + fcx;
    const int ub1 = (og * 4 + 1) * 64 + fcx;
    const int ub2 = (og * 4 + 2) * 64 + fcx;
    const int ub3 = (og * 4 + 3) * 64 + fcx;

    for (int t = blockIdx.x; t < NTILES; t += GX) {
        const int rb = t * 64 + w * 8;

        const ulonglong2* pr[4];
        int rows[4];
#pragma unroll
        for (int rp = 0; rp < 4; rp++) {
            int r = rb + rp * 2 + rl;
            rows[rp] = r;
            int rc = r < NN ? r : NN - 1;
            pr[rp] = (const ulonglong2*)(chb + (size_t)rc * FIN) + fc;
        }

        ull acc[4][4];
#pragma unroll
        for (int rp = 0; rp < 4; rp++)
#pragma unroll
            for (int k = 0; k < 4; k++) acc[rp][k] = 0ull;

        // Prefetch fi = 0.
        ulonglong2 cur[4];
#pragma unroll
        for (int rp = 0; rp < 4; rp++) cur[rp] = pr[rp][0];

#pragma unroll 4
        for (int fi = 0; fi < 16; fi++) {
            ulonglong2 nxt[4];
            if (fi < 15) {
#pragma unroll
                for (int rp = 0; rp < 4; rp++) nxt[rp] = pr[rp][(fi + 1) * 4];
            }
            const int fs = fi * 4;
            ulonglong2 u0 = us[ub0 + fs];
            ulonglong2 u1 = us[ub1 + fs];
            ulonglong2 u2 = us[ub2 + fs];
            ulonglong2 u3 = us[ub3 + fs];

#pragma unroll
            for (int rp = 0; rp < 4; rp++) {
                fma2(acc[rp][0], cur[rp].x, u0.x); fma2(acc[rp][0], cur[rp].y, u0.y);
                fma2(acc[rp][1], cur[rp].x, u1.x); fma2(acc[rp][1], cur[rp].y, u1.y);
                fma2(acc[rp][2], cur[rp].x, u2.x); fma2(acc[rp][2], cur[rp].y, u2.y);
                fma2(acc[rp][3], cur[rp].x, u3.x); fma2(acc[rp][3], cur[rp].y, u3.y);
            }
            if (fi < 15) {
#pragma unroll
                for (int rp = 0; rp < 4; rp++) cur[rp] = nxt[rp];
            }
        }

        // Epilogue: packed-halves add, reduce over fc lanes (bits 3-4), store.
#pragma unroll
        for (int rp = 0; rp < 4; rp++) {
            float v[4];
#pragma unroll
            for (int k = 0; k < 4; k++) {
                float lo, hi; upk2(acc[rp][k], lo, hi);
                v[k] = lo + hi;
            }
#pragma unroll
            for (int k = 0; k < 4; k++) {
                v[k] += __shfl_xor_sync(0xffffffffu, v[k], 8);
                v[k] += __shfl_xor_sync(0xffffffffu, v[k], 16);
            }
            if (fc == 0 && rows[rp] < NN) {
                float4 o4 = make_float4(v[0], v[1], v[2], v[3]);
                *(float4*)&g_scores[s_tab][((size_t)b * NN + rows[rp]) * NH + hoff] = o4;
            }
        }
    }
}

// ---------------------------------------------------------------------------
// K3: out[i] = sigmoid(scores_src[head[i]] + scores_trg[tail[i]])
// 4 edges per thread: good MLP, 2x the warps of the 8/thread version.
// ---------------------------------------------------------------------------
__global__ void k_gather(const void* __restrict__ head,
                         const void* __restrict__ tail,
                         float* __restrict__ out, int total) {
    int i = blockIdx.x * blockDim.x + threadIdx.x;   // group of 4 edges
    if (i * 4 >= total) return;

    long long h[4], t[4];
    if (g_idx_is64) {
        longlong2 a0 = ((const longlong2*)head)[2 * i];
        longlong2 a1 = ((const longlong2*)head)[2 * i + 1];
        longlong2 b0 = ((const longlong2*)tail)[2 * i];
        longlong2 b1 = ((const longlong2*)tail)[2 * i + 1];
        h[0] = a0.x; h[1] = a0.y; h[2] = a1.x; h[3] = a1.y;
        t[0] = b0.x; t[1] = b0.y; t[2] = b1.x; t[3] = b1.y;
    } else {
        int4 a = ((const int4*)head)[i];
        int4 c = ((const int4*)tail)[i];
        h[0] = a.x; h[1] = a.y; h[2] = a.z; h[3] = a.w;
        t[0] = c.x; t[1] = c.y; t[2] = c.z; t[3] = c.w;
    }

    float sh[4], st[4];
#pragma unroll
    for (int k = 0; k < 4; k++) sh[k] = g_scores[0][h[k]];
#pragma unroll
    for (int k = 0; k < 4; k++) st[k] = g_scores[1][t[k]];

    float4 r;
    r.x = 1.f / (1.f + __expf(-(sh[0] + st[0])));
    r.y = 1.f / (1.f + __expf(-(sh[1] + st[1])));
    r.z = 1.f / (1.f + __expf(-(sh[2] + st[2])));
    r.w = 1.f / (1.f + __expf(-(sh[3] + st[3])));
    ((float4*)out)[i] = r;
}

// ---------------------------------------------------------------------------
extern "C" void kernel_launch(void* const* d_in, const int* in_sizes, int n_in,
                              void* d_out, int out_size) {
    const float* ch   = (const float*)d_in[0];
    const void*  head = d_in[1];
    const void*  tail = d_in[2];
    const float* W    = (const float*)d_in[3];
    const float* src  = (const float*)d_in[4];
    const float* trg  = (const float*)d_in[5];
    float* out = (float*)d_out;

    k_sniff<<<1, 256>>>((const unsigned int*)head);
    k_prep<<<BSZ * 2 * NH, 256>>>(W, src, trg);

    dim3 g2(GX, BSZ);
    k_scores<<<g2, 256>>>(ch);

    int total = BSZ * EE;                       // 1,280,000 (multiple of 4)
    int groups = total / 4;
    k_gather<<<(groups + 255) / 256, 256>>>(head, tail, out, total);
}